// round 10
// baseline (speedup 1.0000x reference)
#include <cuda_runtime.h>

// x is [B, T] float32.
#define BB 64
#define TT 262144
#define BLK 8192                   // samples per block (8 warps x 1024)
#define CPBR 32                    // blocks per row
#define NBLK 2048
#define WSPAN 1024
#define TILES 4                    // 4 tiles of 256 samples per warp (8/lane)

// Decoupled-lookback state (u-space complex, fp32 value + int flag).
__device__ float2 g_agg[NBLK];
__device__ float2 g_incl[NBLK];
__device__ int    g_flag[NBLK];    // 0 = none, 1 = aggregate, 2 = inclusive

struct SC {
    float2 lvl[5];     // c^(8*2^r)
    float2 ilvl[5];    // c^(-8*2^r)
    float2 i8;         // c^-8
    float2 c256;       // per-tile advance
    float  alpha, beta, invbeta;
    float  na1, na2, b0, b1, b2;
    double c1024r, c1024i;   // per-warp-span advance (double)
    double c8192r, c8192i;   // per-block advance (double)
};

__device__ __forceinline__ void build_sc(const float* ac, const float* bc, SC* sc) {
    double a0 = (double)ac[0];
    double a1 = (double)ac[1] / a0, a2 = (double)ac[2] / a0;
    double al = -0.5 * a1;
    double be = sqrt(a2 - al * al);
    sc->alpha = (float)al; sc->beta = (float)be; sc->invbeta = (float)(1.0 / be);
    sc->na1 = (float)(-a1); sc->na2 = (float)(-a2);
    sc->b0 = (float)((double)bc[0] / a0);
    sc->b1 = (float)((double)bc[1] / a0);
    sc->b2 = (float)((double)bc[2] / a0);

    double cr = al, ci = be;   // c
    for (int i = 0; i < 3; ++i) { double nr = cr*cr - ci*ci, ni = 2.0*cr*ci; cr = nr; ci = ni; } // c^8
    for (int r = 0; r < 5; ++r) {
        sc->lvl[r] = make_float2((float)cr, (float)ci);
        double n = cr*cr + ci*ci;
        sc->ilvl[r] = make_float2((float)(cr / n), (float)(-ci / n));
        if (r == 0) sc->i8 = sc->ilvl[0];
        double nr = cr*cr - ci*ci, ni = 2.0*cr*ci; cr = nr; ci = ni;
    }
    sc->c256 = make_float2((float)cr, (float)ci);                       // c^256
    { double nr = cr*cr - ci*ci, ni = 2.0*cr*ci; cr = nr; ci = ni; }    // c^512
    { double nr = cr*cr - ci*ci, ni = 2.0*cr*ci; cr = nr; ci = ni; }    // c^1024
    sc->c1024r = cr; sc->c1024i = ci;
    for (int i = 0; i < 3; ++i) { double nr = cr*cr - ci*ci, ni = 2.0*cr*ci; cr = nr; ci = ni; } // c^8192
    sc->c8192r = cr; sc->c8192i = ci;
}

__device__ __forceinline__ float2 cmulf(float2 a, float2 b) {
    return make_float2(fmaf(a.x, b.x, -a.y * b.y), fmaf(a.x, b.y, a.y * b.x));
}

#define FIR8(f, va, vb, xm1, xm2, b0, b1, b2)                         \
    f[0] = fmaf(b1, xm1,  fmaf(b2, xm2,  b0 * va.x));                 \
    f[1] = fmaf(b1, va.x, fmaf(b2, xm1,  b0 * va.y));                 \
    f[2] = fmaf(b1, va.y, fmaf(b2, va.x, b0 * va.z));                 \
    f[3] = fmaf(b1, va.z, fmaf(b2, va.y, b0 * va.w));                 \
    f[4] = fmaf(b1, va.w, fmaf(b2, va.z, b0 * vb.x));                 \
    f[5] = fmaf(b1, vb.x, fmaf(b2, va.w, b0 * vb.y));                 \
    f[6] = fmaf(b1, vb.y, fmaf(b2, vb.x, b0 * vb.z));                 \
    f[7] = fmaf(b1, vb.z, fmaf(b2, vb.y, b0 * vb.w));

#define IIR8(y, f, na1, na2)                                          \
    y[0] = f[0];                                                      \
    y[1] = fmaf(na1, y[0], f[1]);                                     \
    y[2] = fmaf(na1, y[1], fmaf(na2, y[0], f[2]));                    \
    y[3] = fmaf(na1, y[2], fmaf(na2, y[1], f[3]));                    \
    y[4] = fmaf(na1, y[3], fmaf(na2, y[2], f[4]));                    \
    y[5] = fmaf(na1, y[4], fmaf(na2, y[3], f[5]));                    \
    y[6] = fmaf(na1, y[5], fmaf(na2, y[4], f[6]));                    \
    y[7] = fmaf(na1, y[6], fmaf(na2, y[5], f[7]));

__global__ __launch_bounds__(256, 4) void k_main(
    const float* __restrict__ x,
    const float* __restrict__ ac,
    const float* __restrict__ bc,
    const float* __restrict__ gainp,
    float* __restrict__ out)
{
    __shared__ SC sc;
    __shared__ float   sx[BLK];        // 32 KB x tile
    __shared__ float2  sWarpAgg[8];    // per-warp zero-IC u totals (S_w)
    __shared__ double2 sE[8];          // zero-IC u state entering warp w (E_w)
    __shared__ float2  sEntry[8];      // corrected u entry per warp

    int tid = threadIdx.x;
    int w = tid >> 5, lane = tid & 31;
    int bid = blockIdx.x;
    int row = bid >> 5, blkInRow = bid & 31;
    size_t base = (size_t)row * TT + (size_t)blkInRow * BLK;

    // Stage x -> smem, coalesced.
    {
        const float4* gx = reinterpret_cast<const float4*>(x + base);
        float4* s4 = reinterpret_cast<float4*>(sx);
        for (int i = tid; i < BLK / 4; i += 256) s4[i] = gx[i];
    }
    if (tid == 0) build_sc(ac, bc, &sc);
    __syncthreads();

    float na1 = sc.na1, na2 = sc.na2, b0 = sc.b0, b1 = sc.b1, b2 = sc.b2;
    float alpha = sc.alpha, beta = sc.beta, invbeta = sc.invbeta;
    float2 c256 = sc.c256;

    // Per-lane basis constants.
    float2 sd = sc.i8, su = make_float2(1.f, 0.f);
    if (lane & 1)  { sd = cmulf(sd, sc.ilvl[0]); su = cmulf(su, sc.lvl[0]); }
    if (lane & 2)  { sd = cmulf(sd, sc.ilvl[1]); su = cmulf(su, sc.lvl[1]); }
    if (lane & 4)  { sd = cmulf(sd, sc.ilvl[2]); su = cmulf(su, sc.lvl[2]); }
    if (lane & 8)  { sd = cmulf(sd, sc.ilvl[3]); su = cmulf(su, sc.lvl[3]); }
    if (lane & 16) { sd = cmulf(sd, sc.ilvl[4]); su = cmulf(su, sc.lvl[4]); }

    const float4* sxv = reinterpret_cast<const float4*>(sx) + w * (WSPAN / 4);

    // Boundary x for this warp's span.
    float bx1, bx2;
    if (w == 0) {
        if (blkInRow) { bx1 = x[base - 1]; bx2 = x[base - 2]; }
        else          { bx1 = 0.f; bx2 = 0.f; }
    } else {
        bx1 = sx[w * WSPAN - 1]; bx2 = sx[w * WSPAN - 2];
    }

    // ---------------- Phase A: zero-IC reduce over the warp span ----------------
    {
        float pv_w = bx1, pv_z = bx2;
        float2 C = make_float2(0.f, 0.f);
#pragma unroll
        for (int t = 0; t < TILES; ++t) {
            float4 va = sxv[t * 64 + 2 * lane];
            float4 vb = sxv[t * 64 + 2 * lane + 1];
            float xm1 = __shfl_up_sync(0xffffffffu, vb.w, 1);
            float xm2 = __shfl_up_sync(0xffffffffu, vb.z, 1);
            if (lane == 0) { xm1 = pv_w; xm2 = pv_z; }

            float f[8], y[8];
            FIR8(f, va, vb, xm1, xm2, b0, b1, b2);
            IIR8(y, f, na1, na2);

            float2 u = make_float2(y[6], fmaf(alpha, y[6], -y[7]) * invbeta);
            float2 ww = cmulf(u, sd);
#pragma unroll
            for (int s = 16; s > 0; s >>= 1) {
                ww.x += __shfl_down_sync(0xffffffffu, ww.x, s);
                ww.y += __shfl_down_sync(0xffffffffu, ww.y, s);
            }
            float Sx = __shfl_sync(0xffffffffu, ww.x, 0);
            float Sy = __shfl_sync(0xffffffffu, ww.y, 0);
            C = cmulf(make_float2(C.x + Sx, C.y + Sy), c256);

            pv_w = __shfl_sync(0xffffffffu, vb.w, 31);
            pv_z = __shfl_sync(0xffffffffu, vb.z, 31);
        }
        if (lane == 0) sWarpAgg[w] = C;
    }
    __syncthreads();

    // ---------------- Thread 0: combine, publish, lookback, entries ----------------
    if (tid == 0) {
        double c1r = sc.c1024r, c1i = sc.c1024i;
        double c8r = sc.c8192r, c8i = sc.c8192i;
        double e1 = 0.0, e2 = 0.0;
#pragma unroll
        for (int ww = 0; ww < 8; ++ww) {
            sE[ww] = make_double2(e1, e2);
            float2 S = sWarpAgg[ww];
            double t1 = c1r * e1 - c1i * e2 + (double)S.x;
            double t2 = c1i * e1 + c1r * e2 + (double)S.y;
            e1 = t1; e2 = t2;
        }
        // Block aggregate A = (e1,e2) (u-space).
        g_agg[bid] = make_float2((float)e1, (float)e2);
        __threadfence();

        double P1 = 0.0, P2 = 0.0;
        if (blkInRow == 0) {
            g_incl[bid] = make_float2((float)e1, (float)e2);
            __threadfence();
            *(volatile int*)&g_flag[bid] = 2;
        } else {
            *(volatile int*)&g_flag[bid] = 1;
            double M1 = 1.0, M2 = 0.0;
            int j = bid - 1;
            while (true) {
                int f;
                while ((f = *(volatile int*)&g_flag[j]) == 0) __nanosleep(32);
                __threadfence();
                volatile float* vp = (f == 2) ? (volatile float*)&g_incl[j]
                                              : (volatile float*)&g_agg[j];
                double Vx = (double)vp[0], Vy = (double)vp[1];
                P1 += M1 * Vx - M2 * Vy;
                P2 += M1 * Vy + M2 * Vx;
                if (f == 2) break;
                double m1 = M1 * c8r - M2 * c8i;
                M2 = M1 * c8i + M2 * c8r;
                M1 = m1;
                --j;
            }
            // inclusive = c8192 * P + A
            double i1 = c8r * P1 - c8i * P2 + e1;
            double i2 = c8i * P1 + c8r * P2 + e2;
            g_incl[bid] = make_float2((float)i1, (float)i2);
            __threadfence();
            *(volatile int*)&g_flag[bid] = 2;
        }
        // Per-warp corrected entries: entry_w = c^(1024*w) * P + E_w.
        double Q1 = P1, Q2 = P2;
#pragma unroll
        for (int ww = 0; ww < 8; ++ww) {
            double2 E = sE[ww];
            sEntry[ww] = make_float2((float)(Q1 + E.x), (float)(Q2 + E.y));
            double q1 = c1r * Q1 - c1i * Q2;
            Q2 = c1i * Q1 + c1r * Q2;
            Q1 = q1;
        }
    }
    __syncthreads();

    // ---------------- Phase C: corrected recompute + output ----------------
    {
        float gain = gainp[0];
        float2 C = sEntry[w];
        float4* ov = reinterpret_cast<float4*>(out + base + (size_t)w * WSPAN);
        float pv_w = bx1, pv_z = bx2;
#pragma unroll
        for (int t = 0; t < TILES; ++t) {
            float4 va = sxv[t * 64 + 2 * lane];
            float4 vb = sxv[t * 64 + 2 * lane + 1];
            float xm1 = __shfl_up_sync(0xffffffffu, vb.w, 1);
            float xm2 = __shfl_up_sync(0xffffffffu, vb.z, 1);
            if (lane == 0) { xm1 = pv_w; xm2 = pv_z; }

            float f[8], y[8];
            FIR8(f, va, vb, xm1, xm2, b0, b1, b2);
            IIR8(y, f, na1, na2);

            float2 u = make_float2(y[6], fmaf(alpha, y[6], -y[7]) * invbeta);
            float2 ww2 = cmulf(u, sd);
#pragma unroll
            for (int s = 1; s < 32; s <<= 1) {
                float px = __shfl_up_sync(0xffffffffu, ww2.x, s);
                float py = __shfl_up_sync(0xffffffffu, ww2.y, s);
                if (lane >= s) { ww2.x += px; ww2.y += py; }
            }
            float Sx = __shfl_sync(0xffffffffu, ww2.x, 31);
            float Sy = __shfl_sync(0xffffffffu, ww2.y, 31);
            float ex = __shfl_up_sync(0xffffffffu, ww2.x, 1);
            float ey = __shfl_up_sync(0xffffffffu, ww2.y, 1);
            if (lane == 0) { ex = 0.f; ey = 0.f; }

            float2 e = cmulf(make_float2(C.x + ex, C.y + ey), su);
            float yp1 = fmaf(alpha, e.x, -beta * e.y);
            float yp2 = e.x;

            float z0 = fmaf(na1, yp1, fmaf(na2, yp2, f[0]));
            float z1 = fmaf(na1, z0, fmaf(na2, yp1, f[1]));
            float z2 = fmaf(na1, z1, fmaf(na2, z0, f[2]));
            float z3 = fmaf(na1, z2, fmaf(na2, z1, f[3]));
            float z4 = fmaf(na1, z3, fmaf(na2, z2, f[4]));
            float z5 = fmaf(na1, z4, fmaf(na2, z3, f[5]));
            float z6 = fmaf(na1, z5, fmaf(na2, z4, f[6]));
            float z7 = fmaf(na1, z6, fmaf(na2, z5, f[7]));

            float4 oa, ob;
            oa.x = gain * fminf(1.f, fmaxf(-1.f, z0));
            oa.y = gain * fminf(1.f, fmaxf(-1.f, z1));
            oa.z = gain * fminf(1.f, fmaxf(-1.f, z2));
            oa.w = gain * fminf(1.f, fmaxf(-1.f, z3));
            ob.x = gain * fminf(1.f, fmaxf(-1.f, z4));
            ob.y = gain * fminf(1.f, fmaxf(-1.f, z5));
            ob.z = gain * fminf(1.f, fmaxf(-1.f, z6));
            ob.w = gain * fminf(1.f, fmaxf(-1.f, z7));
            ov[t * 64 + 2 * lane]     = oa;
            ov[t * 64 + 2 * lane + 1] = ob;

            C = cmulf(make_float2(C.x + Sx, C.y + Sy), c256);

            pv_w = __shfl_sync(0xffffffffu, vb.w, 31);
            pv_z = __shfl_sync(0xffffffffu, vb.z, 31);
        }
    }
}

extern "C" void kernel_launch(void* const* d_in, const int* in_sizes, int n_in,
                              void* d_out, int out_size)
{
    const float* x    = (const float*)d_in[0];
    const float* ac   = (const float*)d_in[1];
    const float* bc   = (const float*)d_in[2];
    const float* gain = (const float*)d_in[3];
    float* out = (float*)d_out;

    int* flagp;
    cudaGetSymbolAddress((void**)&flagp, g_flag);
    cudaMemsetAsync(flagp, 0, NBLK * sizeof(int));
    k_main<<<NBLK, 256>>>(x, ac, bc, gain, out);
}

// round 11
// speedup vs baseline: 1.7772x; 1.7772x over previous
#include <cuda_runtime.h>

// x is [B, T] float32.
#define BB 64
#define TT 262144
#define WSPAN 1024                 // samples per warp
#define TILES 4                    // 4 serial tiles of 256 samples (8/lane)
#define CPR (TT / WSPAN)           // 256 chunks per row
#define NW (BB * CPR)              // 16384 warps
#define WPB 8                      // warps per block (256 threads)
#define NBLK (NW / WPB)            // 2048 blocks

// Chunk end states (zero-IC) / corrected start states, y-space FLOAT:
// (y[last], y[last-1]) resp. (y[-1], y[-2]).  pass2 combines in double.
__device__ float2 g_end[NW];
__device__ float2 g_start[NW];

struct SC {
    float2 lvl[5];     // c^(8*2^r), r=0..4
    float2 ilvl[5];    // c^(-8*2^r)
    float2 i8;         // c^-8
    float2 c256;       // c^256 (tile advance)
    float  alpha, beta, invbeta;
    float  na1, na2, b0, b1, b2;
};

__device__ __forceinline__ void build_sc(const float* ac, const float* bc, SC* sc) {
    double a0 = (double)ac[0];
    double a1 = (double)ac[1] / a0, a2 = (double)ac[2] / a0;
    double al = -0.5 * a1;
    double be = sqrt(a2 - al * al);          // r*sin(theta) > 0
    sc->alpha = (float)al; sc->beta = (float)be; sc->invbeta = (float)(1.0 / be);
    sc->na1 = (float)(-a1); sc->na2 = (float)(-a2);
    sc->b0 = (float)((double)bc[0] / a0);
    sc->b1 = (float)((double)bc[1] / a0);
    sc->b2 = (float)((double)bc[2] / a0);

    double cr = al, ci = be;                 // c
    for (int i = 0; i < 3; ++i) { double nr = cr*cr - ci*ci, ni = 2.0*cr*ci; cr = nr; ci = ni; } // c^8
    for (int r = 0; r < 5; ++r) {
        sc->lvl[r] = make_float2((float)cr, (float)ci);
        double n = cr*cr + ci*ci;            // inverse = conj/|.|^2
        sc->ilvl[r] = make_float2((float)(cr / n), (float)(-ci / n));
        if (r == 0) sc->i8 = sc->ilvl[0];
        double nr = cr*cr - ci*ci, ni = 2.0*cr*ci; cr = nr; ci = ni;
    }
    sc->c256 = make_float2((float)cr, (float)ci);   // c^256
}

__device__ __forceinline__ float2 cmulf(float2 a, float2 b) {
    return make_float2(fmaf(a.x, b.x, -a.y * b.y), fmaf(a.x, b.y, a.y * b.x));
}

#define FIR8(f, va, vb, xm1, xm2, b0, b1, b2)                         \
    f[0] = fmaf(b1, xm1,  fmaf(b2, xm2,  b0 * va.x));                 \
    f[1] = fmaf(b1, va.x, fmaf(b2, xm1,  b0 * va.y));                 \
    f[2] = fmaf(b1, va.y, fmaf(b2, va.x, b0 * va.z));                 \
    f[3] = fmaf(b1, va.z, fmaf(b2, va.y, b0 * va.w));                 \
    f[4] = fmaf(b1, va.w, fmaf(b2, va.z, b0 * vb.x));                 \
    f[5] = fmaf(b1, vb.x, fmaf(b2, va.w, b0 * vb.y));                 \
    f[6] = fmaf(b1, vb.y, fmaf(b2, vb.x, b0 * vb.z));                 \
    f[7] = fmaf(b1, vb.z, fmaf(b2, vb.y, b0 * vb.w));

#define IIR8(y, f, na1, na2)                                          \
    y[0] = f[0];                                                      \
    y[1] = fmaf(na1, y[0], f[1]);                                     \
    y[2] = fmaf(na1, y[1], fmaf(na2, y[0], f[2]));                    \
    y[3] = fmaf(na1, y[2], fmaf(na2, y[1], f[3]));                    \
    y[4] = fmaf(na1, y[3], fmaf(na2, y[2], f[4]));                    \
    y[5] = fmaf(na1, y[4], fmaf(na2, y[3], f[5]));                    \
    y[6] = fmaf(na1, y[5], fmaf(na2, y[4], f[6]));                    \
    y[7] = fmaf(na1, y[6], fmaf(na2, y[5], f[7]));

// ---------------------------------------------------------------------------
// Pass 1: per-warp zero-IC end state. All-fp32 scaled-basis reduce, depth-3
// load pipeline: tiles 0..2 preloaded, tile t+3 prefetched during tile t.
// ---------------------------------------------------------------------------
__global__ __launch_bounds__(256, 4) void k_pass1(
    const float* __restrict__ x,
    const float* __restrict__ ac,
    const float* __restrict__ bc)
{
    __shared__ SC sc;
    if (threadIdx.x == 0) build_sc(ac, bc, &sc);
    __syncthreads();

    int wid = blockIdx.x * WPB + (threadIdx.x >> 5);
    int lane = threadIdx.x & 31;
    int row = wid / CPR, chunk = wid - row * CPR;
    size_t wbase = (size_t)row * TT + (size_t)chunk * WSPAN;
    const float4* xv = reinterpret_cast<const float4*>(x + wbase);

    float na1 = sc.na1, na2 = sc.na2, b0 = sc.b0, b1 = sc.b1, b2 = sc.b2;
    float alpha = sc.alpha, beta = sc.beta, invbeta = sc.invbeta;
    float2 c256 = sc.c256;

    // sd = c^(-8*(lane+1))
    float2 sd = sc.i8;
    if (lane & 1)  sd = cmulf(sd, sc.ilvl[0]);
    if (lane & 2)  sd = cmulf(sd, sc.ilvl[1]);
    if (lane & 4)  sd = cmulf(sd, sc.ilvl[2]);
    if (lane & 8)  sd = cmulf(sd, sc.ilvl[3]);
    if (lane & 16) sd = cmulf(sd, sc.ilvl[4]);

    float pv_w = 0.f, pv_z = 0.f;
    if (chunk) { pv_w = x[wbase - 1]; pv_z = x[wbase - 2]; }

    float2 C = make_float2(0.f, 0.f);   // u-space carry, fp32

    // Depth-3 pipeline buffers (tiles 0..2 in flight before compute starts).
    float4 pa[3], pb[3];
#pragma unroll
    for (int i = 0; i < 3; ++i) {
        pa[i] = xv[i * 64 + 2 * lane];
        pb[i] = xv[i * 64 + 2 * lane + 1];
    }
#pragma unroll
    for (int t = 0; t < TILES; ++t) {
        float4 va = pa[t % 3], vb = pb[t % 3];
        if (t + 3 < TILES) {
            pa[(t + 3) % 3] = xv[(t + 3) * 64 + 2 * lane];
            pb[(t + 3) % 3] = xv[(t + 3) * 64 + 2 * lane + 1];
        }
        float xm1 = __shfl_up_sync(0xffffffffu, vb.w, 1);
        float xm2 = __shfl_up_sync(0xffffffffu, vb.z, 1);
        if (lane == 0) { xm1 = pv_w; xm2 = pv_z; }

        float f[8], y[8];
        FIR8(f, va, vb, xm1, xm2, b0, b1, b2);
        IIR8(y, f, na1, na2);

        float2 u = make_float2(y[6], fmaf(alpha, y[6], -y[7]) * invbeta);
        float2 w = cmulf(u, sd);

#pragma unroll
        for (int s = 16; s > 0; s >>= 1) {
            w.x += __shfl_down_sync(0xffffffffu, w.x, s);
            w.y += __shfl_down_sync(0xffffffffu, w.y, s);
        }
        float Sx = __shfl_sync(0xffffffffu, w.x, 0);
        float Sy = __shfl_sync(0xffffffffu, w.y, 0);
        C = cmulf(make_float2(C.x + Sx, C.y + Sy), c256);

        pv_w = __shfl_sync(0xffffffffu, vb.w, 31);
        pv_z = __shfl_sync(0xffffffffu, vb.z, 31);
    }
    if (lane == 0) {
        g_end[wid] = make_float2(fmaf(alpha, C.x, -beta * C.y), C.x);
    }
}

// ---------------------------------------------------------------------------
// Pass 2: per-row KS scan over 256 chunk states in DOUBLE (vector-only),
// level matrices Phi^(1024*2^r) by thread 0.  Writes exclusive prefixes.
// ---------------------------------------------------------------------------
__global__ __launch_bounds__(256) void k_pass2(const float* __restrict__ ac)
{
    __shared__ double2 sV[CPR];
    __shared__ double  sLev[8 * 4];
    int row = blockIdx.x, tid = threadIdx.x;

    if (tid == 0) {
        double a0 = (double)ac[0];
        double a1 = (double)ac[1] / a0, a2 = (double)ac[2] / a0;
        double m11 = -a1, m12 = -a2, m21 = 1.0, m22 = 0.0;
        for (int i = 0; i < 10; ++i) {   // Phi^1024
            double n11 = m11*m11 + m12*m21, n12 = m11*m12 + m12*m22;
            double n21 = m21*m11 + m22*m21, n22 = m21*m12 + m22*m22;
            m11 = n11; m12 = n12; m21 = n21; m22 = n22;
        }
        sLev[0] = m11; sLev[1] = m12; sLev[2] = m21; sLev[3] = m22;
        for (int r = 1; r < 8; ++r) {
            double n11 = m11*m11 + m12*m21, n12 = m11*m12 + m12*m22;
            double n21 = m21*m11 + m22*m21, n22 = m21*m12 + m22*m22;
            m11 = n11; m12 = n12; m21 = n21; m22 = n22;
            sLev[r*4+0] = m11; sLev[r*4+1] = m12; sLev[r*4+2] = m21; sLev[r*4+3] = m22;
        }
    }
    float2 e = g_end[row * CPR + tid];
    double v1 = (double)e.x, v2 = (double)e.y;
    __syncthreads();

#pragma unroll
    for (int r = 0; r < 8; ++r) {
        sV[tid] = make_double2(v1, v2);
        __syncthreads();
        int src = tid - (1 << r);
        double2 vp;
        bool has = (src >= 0);
        if (has) vp = sV[src];
        __syncthreads();
        if (has) {
            double m11 = sLev[r*4+0], m12 = sLev[r*4+1];
            double m21 = sLev[r*4+2], m22 = sLev[r*4+3];
            v1 = m11 * vp.x + m12 * vp.y + v1;
            v2 = m21 * vp.x + m22 * vp.y + v2;
        }
    }
    sV[tid] = make_double2(v1, v2);
    __syncthreads();
    double2 ex = (tid == 0) ? make_double2(0.0, 0.0) : sV[tid - 1];
    g_start[row * CPR + tid] = make_float2((float)ex.x, (float)ex.y);
}

// ---------------------------------------------------------------------------
// Pass 3: corrected recompute, all-fp32, depth-3 load pipeline (__ldcs x),
// streaming output stores (__stcs).
// ---------------------------------------------------------------------------
__global__ __launch_bounds__(256, 4) void k_pass3(
    const float* __restrict__ x,
    const float* __restrict__ ac,
    const float* __restrict__ bc,
    const float* __restrict__ gainp,
    float* __restrict__ out)
{
    __shared__ SC sc;
    if (threadIdx.x == 0) build_sc(ac, bc, &sc);
    __syncthreads();

    int wid = blockIdx.x * WPB + (threadIdx.x >> 5);
    int lane = threadIdx.x & 31;
    int row = wid / CPR, chunk = wid - row * CPR;
    size_t wbase = (size_t)row * TT + (size_t)chunk * WSPAN;
    const float4* xv = reinterpret_cast<const float4*>(x + wbase);
    float4* ov = reinterpret_cast<float4*>(out + wbase);

    float na1 = sc.na1, na2 = sc.na2, b0 = sc.b0, b1 = sc.b1, b2 = sc.b2;
    float alpha = sc.alpha, beta = sc.beta, invbeta = sc.invbeta;
    float gain = gainp[0];
    float2 c256 = sc.c256;

    // sd = c^(-8*(lane+1)); su = c^(8*lane)
    float2 sd = sc.i8, su = make_float2(1.f, 0.f);
    if (lane & 1)  { sd = cmulf(sd, sc.ilvl[0]); su = cmulf(su, sc.lvl[0]); }
    if (lane & 2)  { sd = cmulf(sd, sc.ilvl[1]); su = cmulf(su, sc.lvl[1]); }
    if (lane & 4)  { sd = cmulf(sd, sc.ilvl[2]); su = cmulf(su, sc.lvl[2]); }
    if (lane & 8)  { sd = cmulf(sd, sc.ilvl[3]); su = cmulf(su, sc.lvl[3]); }
    if (lane & 16) { sd = cmulf(sd, sc.ilvl[4]); su = cmulf(su, sc.lvl[4]); }

    float pv_w = 0.f, pv_z = 0.f;
    if (chunk) { pv_w = x[wbase - 1]; pv_z = x[wbase - 2]; }

    float2 S0 = g_start[wid];
    float2 C = make_float2(S0.y, fmaf(alpha, S0.y, -S0.x) * invbeta);

    float4 pa[3], pb[3];
#pragma unroll
    for (int i = 0; i < 3; ++i) {
        pa[i] = __ldcs(&xv[i * 64 + 2 * lane]);
        pb[i] = __ldcs(&xv[i * 64 + 2 * lane + 1]);
    }
#pragma unroll
    for (int t = 0; t < TILES; ++t) {
        float4 va = pa[t % 3], vb = pb[t % 3];
        if (t + 3 < TILES) {
            pa[(t + 3) % 3] = __ldcs(&xv[(t + 3) * 64 + 2 * lane]);
            pb[(t + 3) % 3] = __ldcs(&xv[(t + 3) * 64 + 2 * lane + 1]);
        }
        float xm1 = __shfl_up_sync(0xffffffffu, vb.w, 1);
        float xm2 = __shfl_up_sync(0xffffffffu, vb.z, 1);
        if (lane == 0) { xm1 = pv_w; xm2 = pv_z; }

        float f[8], y[8];
        FIR8(f, va, vb, xm1, xm2, b0, b1, b2);
        IIR8(y, f, na1, na2);

        float2 u = make_float2(y[6], fmaf(alpha, y[6], -y[7]) * invbeta);
        float2 w = cmulf(u, sd);

#pragma unroll
        for (int s = 1; s < 32; s <<= 1) {
            float px = __shfl_up_sync(0xffffffffu, w.x, s);
            float py = __shfl_up_sync(0xffffffffu, w.y, s);
            if (lane >= s) { w.x += px; w.y += py; }
        }
        float Sx = __shfl_sync(0xffffffffu, w.x, 31);
        float Sy = __shfl_sync(0xffffffffu, w.y, 31);
        float ex = __shfl_up_sync(0xffffffffu, w.x, 1);
        float ey = __shfl_up_sync(0xffffffffu, w.y, 1);
        if (lane == 0) { ex = 0.f; ey = 0.f; }

        float2 e = cmulf(make_float2(C.x + ex, C.y + ey), su);
        float yp1 = fmaf(alpha, e.x, -beta * e.y);   // y[n-1]
        float yp2 = e.x;                             // y[n-2]

        float z0 = fmaf(na1, yp1, fmaf(na2, yp2, f[0]));
        float z1 = fmaf(na1, z0, fmaf(na2, yp1, f[1]));
        float z2 = fmaf(na1, z1, fmaf(na2, z0, f[2]));
        float z3 = fmaf(na1, z2, fmaf(na2, z1, f[3]));
        float z4 = fmaf(na1, z3, fmaf(na2, z2, f[4]));
        float z5 = fmaf(na1, z4, fmaf(na2, z3, f[5]));
        float z6 = fmaf(na1, z5, fmaf(na2, z4, f[6]));
        float z7 = fmaf(na1, z6, fmaf(na2, z5, f[7]));

        float4 oa, ob;
        oa.x = gain * fminf(1.f, fmaxf(-1.f, z0));
        oa.y = gain * fminf(1.f, fmaxf(-1.f, z1));
        oa.z = gain * fminf(1.f, fmaxf(-1.f, z2));
        oa.w = gain * fminf(1.f, fmaxf(-1.f, z3));
        ob.x = gain * fminf(1.f, fmaxf(-1.f, z4));
        ob.y = gain * fminf(1.f, fmaxf(-1.f, z5));
        ob.z = gain * fminf(1.f, fmaxf(-1.f, z6));
        ob.w = gain * fminf(1.f, fmaxf(-1.f, z7));
        __stcs(&ov[t * 64 + 2 * lane],     oa);
        __stcs(&ov[t * 64 + 2 * lane + 1], ob);

        C = cmulf(make_float2(C.x + Sx, C.y + Sy), c256);

        pv_w = __shfl_sync(0xffffffffu, vb.w, 31);
        pv_z = __shfl_sync(0xffffffffu, vb.z, 31);
    }
}

extern "C" void kernel_launch(void* const* d_in, const int* in_sizes, int n_in,
                              void* d_out, int out_size)
{
    const float* x    = (const float*)d_in[0];
    const float* ac   = (const float*)d_in[1];
    const float* bc   = (const float*)d_in[2];
    const float* gain = (const float*)d_in[3];
    float* out = (float*)d_out;

    k_pass1<<<NBLK, 256>>>(x, ac, bc);
    k_pass2<<<BB, 256>>>(ac);
    k_pass3<<<NBLK, 256>>>(x, ac, bc, gain, out);
}

// round 12
// speedup vs baseline: 1.9266x; 1.0841x over previous
#include <cuda_runtime.h>

// x is [B, T] float32.
#define BB 64
#define TT 262144
#define BPR 8                      // blocks per row
#define BLK (TT / BPR)             // 32768 samples per block
#define NBLK (BB * BPR)            // 512 blocks — single co-resident wave
#define WSPAN (BLK / 8)            // 4096 samples per warp
#define TILES (WSPAN / 256)        // 16 tiles of 256 samples (8/lane)

// Decoupled-lookback state (u-space complex, fp32 value + int flag).
__device__ float2 g_agg[NBLK];
__device__ float2 g_incl[NBLK];
__device__ int    g_flag[NBLK];    // 0 = none, 1 = aggregate, 2 = inclusive

struct SC {
    float2 lvl[5];     // c^(8*2^r)
    float2 ilvl[5];    // c^(-8*2^r)
    float2 i8;         // c^-8
    float2 c256;       // per-tile advance
    float  alpha, beta, invbeta;
    float  na1, na2, b0, b1, b2;
    double c4096r, c4096i;     // per-warp-span advance (double)
    double cBr, cBi;           // per-block advance c^32768 (double)
};

__device__ __forceinline__ void build_sc(const float* ac, const float* bc, SC* sc) {
    double a0 = (double)ac[0];
    double a1 = (double)ac[1] / a0, a2 = (double)ac[2] / a0;
    double al = -0.5 * a1;
    double be = sqrt(a2 - al * al);
    sc->alpha = (float)al; sc->beta = (float)be; sc->invbeta = (float)(1.0 / be);
    sc->na1 = (float)(-a1); sc->na2 = (float)(-a2);
    sc->b0 = (float)((double)bc[0] / a0);
    sc->b1 = (float)((double)bc[1] / a0);
    sc->b2 = (float)((double)bc[2] / a0);

    double cr = al, ci = be;   // c
    for (int i = 0; i < 3; ++i) { double nr = cr*cr - ci*ci, ni = 2.0*cr*ci; cr = nr; ci = ni; } // c^8
    for (int r = 0; r < 5; ++r) {
        sc->lvl[r] = make_float2((float)cr, (float)ci);
        double n = cr*cr + ci*ci;
        sc->ilvl[r] = make_float2((float)(cr / n), (float)(-ci / n));
        if (r == 0) sc->i8 = sc->ilvl[0];
        double nr = cr*cr - ci*ci, ni = 2.0*cr*ci; cr = nr; ci = ni;
    }
    sc->c256 = make_float2((float)cr, (float)ci);                       // c^256
    for (int i = 0; i < 4; ++i) { double nr = cr*cr - ci*ci, ni = 2.0*cr*ci; cr = nr; ci = ni; } // c^4096
    sc->c4096r = cr; sc->c4096i = ci;
    for (int i = 0; i < 3; ++i) { double nr = cr*cr - ci*ci, ni = 2.0*cr*ci; cr = nr; ci = ni; } // c^32768
    sc->cBr = cr; sc->cBi = ci;
}

__device__ __forceinline__ float2 cmulf(float2 a, float2 b) {
    return make_float2(fmaf(a.x, b.x, -a.y * b.y), fmaf(a.x, b.y, a.y * b.x));
}

#define FIR8(f, va, vb, xm1, xm2, b0, b1, b2)                         \
    f[0] = fmaf(b1, xm1,  fmaf(b2, xm2,  b0 * va.x));                 \
    f[1] = fmaf(b1, va.x, fmaf(b2, xm1,  b0 * va.y));                 \
    f[2] = fmaf(b1, va.y, fmaf(b2, va.x, b0 * va.z));                 \
    f[3] = fmaf(b1, va.z, fmaf(b2, va.y, b0 * va.w));                 \
    f[4] = fmaf(b1, va.w, fmaf(b2, va.z, b0 * vb.x));                 \
    f[5] = fmaf(b1, vb.x, fmaf(b2, va.w, b0 * vb.y));                 \
    f[6] = fmaf(b1, vb.y, fmaf(b2, vb.x, b0 * vb.z));                 \
    f[7] = fmaf(b1, vb.z, fmaf(b2, vb.y, b0 * vb.w));

#define IIR8(y, f, na1, na2)                                          \
    y[0] = f[0];                                                      \
    y[1] = fmaf(na1, y[0], f[1]);                                     \
    y[2] = fmaf(na1, y[1], fmaf(na2, y[0], f[2]));                    \
    y[3] = fmaf(na1, y[2], fmaf(na2, y[1], f[3]));                    \
    y[4] = fmaf(na1, y[3], fmaf(na2, y[2], f[4]));                    \
    y[5] = fmaf(na1, y[4], fmaf(na2, y[3], f[5]));                    \
    y[6] = fmaf(na1, y[5], fmaf(na2, y[4], f[6]));                    \
    y[7] = fmaf(na1, y[6], fmaf(na2, y[5], f[7]));

__global__ __launch_bounds__(256, 4) void k_main(
    const float* __restrict__ x,
    const float* __restrict__ ac,
    const float* __restrict__ bc,
    const float* __restrict__ gainp,
    float* __restrict__ out)
{
    __shared__ SC sc;
    __shared__ float2  sWarpAgg[8];   // per-warp zero-IC u totals
    __shared__ float2  sEntry[8];     // corrected u entry per warp
    __shared__ double2 sE[8];         // zero-IC u state entering warp w

    int tid = threadIdx.x;
    int w = tid >> 5, lane = tid & 31;
    int bid = blockIdx.x;
    int row = bid >> 3, blkInRow = bid & 7;
    size_t base = (size_t)row * TT + (size_t)blkInRow * BLK;

    if (tid == 0) build_sc(ac, bc, &sc);
    __syncthreads();

    float na1 = sc.na1, na2 = sc.na2, b0 = sc.b0, b1 = sc.b1, b2 = sc.b2;
    float alpha = sc.alpha, beta = sc.beta, invbeta = sc.invbeta;
    float2 c256 = sc.c256;

    // Per-lane basis constants.
    float2 sd = sc.i8, su = make_float2(1.f, 0.f);
    if (lane & 1)  { sd = cmulf(sd, sc.ilvl[0]); su = cmulf(su, sc.lvl[0]); }
    if (lane & 2)  { sd = cmulf(sd, sc.ilvl[1]); su = cmulf(su, sc.lvl[1]); }
    if (lane & 4)  { sd = cmulf(sd, sc.ilvl[2]); su = cmulf(su, sc.lvl[2]); }
    if (lane & 8)  { sd = cmulf(sd, sc.ilvl[3]); su = cmulf(su, sc.lvl[3]); }
    if (lane & 16) { sd = cmulf(sd, sc.ilvl[4]); su = cmulf(su, sc.lvl[4]); }

    size_t wstart = base + (size_t)w * WSPAN;
    const float4* xv = reinterpret_cast<const float4*>(x + wstart);

    // Boundary x for this warp's span (global n<0 -> zeros).
    float bx1 = 0.f, bx2 = 0.f;
    if (blkInRow || w) { bx1 = x[wstart - 1]; bx2 = x[wstart - 2]; }

    // ---------------- Phase A: zero-IC reduce over the warp span ----------------
    {
        float pv_w = bx1, pv_z = bx2;
        float2 C = make_float2(0.f, 0.f);
        float4 va = xv[2 * lane], vb = xv[2 * lane + 1];
#pragma unroll 4
        for (int t = 0; t < TILES; ++t) {
            float4 nva, nvb;
            if (t + 1 < TILES) {
                nva = xv[(t + 1) * 64 + 2 * lane];
                nvb = xv[(t + 1) * 64 + 2 * lane + 1];
            }
            float xm1 = __shfl_up_sync(0xffffffffu, vb.w, 1);
            float xm2 = __shfl_up_sync(0xffffffffu, vb.z, 1);
            if (lane == 0) { xm1 = pv_w; xm2 = pv_z; }

            float f[8], y[8];
            FIR8(f, va, vb, xm1, xm2, b0, b1, b2);
            IIR8(y, f, na1, na2);

            float2 u = make_float2(y[6], fmaf(alpha, y[6], -y[7]) * invbeta);
            float2 ww = cmulf(u, sd);
#pragma unroll
            for (int s = 16; s > 0; s >>= 1) {
                ww.x += __shfl_down_sync(0xffffffffu, ww.x, s);
                ww.y += __shfl_down_sync(0xffffffffu, ww.y, s);
            }
            float Sx = __shfl_sync(0xffffffffu, ww.x, 0);
            float Sy = __shfl_sync(0xffffffffu, ww.y, 0);
            C = cmulf(make_float2(C.x + Sx, C.y + Sy), c256);

            pv_w = __shfl_sync(0xffffffffu, vb.w, 31);
            pv_z = __shfl_sync(0xffffffffu, vb.z, 31);
            va = nva; vb = nvb;
        }
        if (lane == 0) sWarpAgg[w] = C;
    }
    __syncthreads();

    // ---------------- Thread 0: combine, publish, lookback, entries ----------------
    if (tid == 0) {
        double c4r = sc.c4096r, c4i = sc.c4096i;
        double cbr = sc.cBr, cbi = sc.cBi;
        double e1 = 0.0, e2 = 0.0;
#pragma unroll
        for (int ww = 0; ww < 8; ++ww) {
            sE[ww] = make_double2(e1, e2);
            float2 S = sWarpAgg[ww];
            double t1 = c4r * e1 - c4i * e2 + (double)S.x;
            double t2 = c4i * e1 + c4r * e2 + (double)S.y;
            e1 = t1; e2 = t2;
        }
        g_agg[bid] = make_float2((float)e1, (float)e2);
        __threadfence();

        double P1 = 0.0, P2 = 0.0;
        if (blkInRow == 0) {
            g_incl[bid] = make_float2((float)e1, (float)e2);
            __threadfence();
            *(volatile int*)&g_flag[bid] = 2;
        } else {
            *(volatile int*)&g_flag[bid] = 1;
            double M1 = 1.0, M2 = 0.0;
            int j = bid - 1;
            while (true) {
                int f;
                while ((f = *(volatile int*)&g_flag[j]) == 0) __nanosleep(32);
                __threadfence();
                volatile float* vp = (f == 2) ? (volatile float*)&g_incl[j]
                                              : (volatile float*)&g_agg[j];
                double Vx = (double)vp[0], Vy = (double)vp[1];
                P1 += M1 * Vx - M2 * Vy;
                P2 += M1 * Vy + M2 * Vx;
                if (f == 2) break;
                double m1 = M1 * cbr - M2 * cbi;
                M2 = M1 * cbi + M2 * cbr;
                M1 = m1;
                --j;
            }
            double i1 = cbr * P1 - cbi * P2 + e1;
            double i2 = cbi * P1 + cbr * P2 + e2;
            g_incl[bid] = make_float2((float)i1, (float)i2);
            __threadfence();
            *(volatile int*)&g_flag[bid] = 2;
        }
        // Per-warp corrected entries: entry_w = c^(4096*w) * P + E_w.
        double Q1 = P1, Q2 = P2;
#pragma unroll
        for (int ww = 0; ww < 8; ++ww) {
            double2 E = sE[ww];
            sEntry[ww] = make_float2((float)(Q1 + E.x), (float)(Q2 + E.y));
            double q1 = c4r * Q1 - c4i * Q2;
            Q2 = c4i * Q1 + c4r * Q2;
            Q1 = q1;
        }
    }
    __syncthreads();

    // ---------------- Phase C: corrected recompute + output ----------------
    {
        float gain = gainp[0];
        float2 C = sEntry[w];
        float4* ov = reinterpret_cast<float4*>(out + wstart);
        float pv_w = bx1, pv_z = bx2;
        float4 va = xv[2 * lane], vb = xv[2 * lane + 1];
#pragma unroll 4
        for (int t = 0; t < TILES; ++t) {
            float4 nva, nvb;
            if (t + 1 < TILES) {
                nva = xv[(t + 1) * 64 + 2 * lane];
                nvb = xv[(t + 1) * 64 + 2 * lane + 1];
            }
            float xm1 = __shfl_up_sync(0xffffffffu, vb.w, 1);
            float xm2 = __shfl_up_sync(0xffffffffu, vb.z, 1);
            if (lane == 0) { xm1 = pv_w; xm2 = pv_z; }

            float f[8], y[8];
            FIR8(f, va, vb, xm1, xm2, b0, b1, b2);
            IIR8(y, f, na1, na2);

            float2 u = make_float2(y[6], fmaf(alpha, y[6], -y[7]) * invbeta);
            float2 ww2 = cmulf(u, sd);
#pragma unroll
            for (int s = 1; s < 32; s <<= 1) {
                float px = __shfl_up_sync(0xffffffffu, ww2.x, s);
                float py = __shfl_up_sync(0xffffffffu, ww2.y, s);
                if (lane >= s) { ww2.x += px; ww2.y += py; }
            }
            float Sx = __shfl_sync(0xffffffffu, ww2.x, 31);
            float Sy = __shfl_sync(0xffffffffu, ww2.y, 31);
            float ex = __shfl_up_sync(0xffffffffu, ww2.x, 1);
            float ey = __shfl_up_sync(0xffffffffu, ww2.y, 1);
            if (lane == 0) { ex = 0.f; ey = 0.f; }

            float2 e = cmulf(make_float2(C.x + ex, C.y + ey), su);
            float yp1 = fmaf(alpha, e.x, -beta * e.y);
            float yp2 = e.x;

            float z0 = fmaf(na1, yp1, fmaf(na2, yp2, f[0]));
            float z1 = fmaf(na1, z0, fmaf(na2, yp1, f[1]));
            float z2 = fmaf(na1, z1, fmaf(na2, z0, f[2]));
            float z3 = fmaf(na1, z2, fmaf(na2, z1, f[3]));
            float z4 = fmaf(na1, z3, fmaf(na2, z2, f[4]));
            float z5 = fmaf(na1, z4, fmaf(na2, z3, f[5]));
            float z6 = fmaf(na1, z5, fmaf(na2, z4, f[6]));
            float z7 = fmaf(na1, z6, fmaf(na2, z5, f[7]));

            float4 oa, ob;
            oa.x = gain * fminf(1.f, fmaxf(-1.f, z0));
            oa.y = gain * fminf(1.f, fmaxf(-1.f, z1));
            oa.z = gain * fminf(1.f, fmaxf(-1.f, z2));
            oa.w = gain * fminf(1.f, fmaxf(-1.f, z3));
            ob.x = gain * fminf(1.f, fmaxf(-1.f, z4));
            ob.y = gain * fminf(1.f, fmaxf(-1.f, z5));
            ob.z = gain * fminf(1.f, fmaxf(-1.f, z6));
            ob.w = gain * fminf(1.f, fmaxf(-1.f, z7));
            __stcs(&ov[t * 64 + 2 * lane],     oa);
            __stcs(&ov[t * 64 + 2 * lane + 1], ob);

            C = cmulf(make_float2(C.x + Sx, C.y + Sy), c256);

            pv_w = __shfl_sync(0xffffffffu, vb.w, 31);
            pv_z = __shfl_sync(0xffffffffu, vb.z, 31);
            va = nva; vb = nvb;
        }
    }
}

extern "C" void kernel_launch(void* const* d_in, const int* in_sizes, int n_in,
                              void* d_out, int out_size)
{
    const float* x    = (const float*)d_in[0];
    const float* ac   = (const float*)d_in[1];
    const float* bc   = (const float*)d_in[2];
    const float* gain = (const float*)d_in[3];
    float* out = (float*)d_out;

    int* flagp;
    cudaGetSymbolAddress((void**)&flagp, g_flag);
    cudaMemsetAsync(flagp, 0, NBLK * sizeof(int));
    k_main<<<NBLK, 256>>>(x, ac, bc, gain, out);
}

// round 13
// speedup vs baseline: 1.9967x; 1.0364x over previous
#include <cuda_runtime.h>

// x is [B, T] float32.
#define BB 64
#define TT 262144
#define BPR 8                      // blocks per row
#define BLK (TT / BPR)             // 32768 samples per block
#define NBLK (BB * BPR)            // 512 blocks — single co-resident wave
#define WSPAN (BLK / 8)            // 4096 samples per warp
#define TILES (WSPAN / 256)        // 16 tiles of 256 samples (8/lane)

// Decoupled-lookback state (u-space complex, fp32 value + int flag).
__device__ float2 g_agg[NBLK];
__device__ float2 g_incl[NBLK];
__device__ int    g_flag[NBLK];    // 0 = none, 1 = aggregate, 2 = inclusive

struct SC {
    float2 lvl[5];     // c^(8*2^r)
    float2 ilvl[5];    // c^(-8*2^r)
    float2 i8;         // c^-8
    float2 c8;         // c^8
    float2 c256;       // per-tile advance
    float2 ic256;      // c^-256
    float2 K0;         // c^(8*511) — phase-A accumulate start constant
    float  alpha, beta, invbeta;
    float  na1, na2, b0, b1, b2;
    double c4096r, c4096i;     // per-warp-span advance (double)
    double cBr, cBi;           // per-block advance c^32768 (double)
};

__device__ __forceinline__ void build_sc(const float* ac, const float* bc, SC* sc) {
    double a0 = (double)ac[0];
    double a1 = (double)ac[1] / a0, a2 = (double)ac[2] / a0;
    double al = -0.5 * a1;
    double be = sqrt(a2 - al * al);
    sc->alpha = (float)al; sc->beta = (float)be; sc->invbeta = (float)(1.0 / be);
    sc->na1 = (float)(-a1); sc->na2 = (float)(-a2);
    sc->b0 = (float)((double)bc[0] / a0);
    sc->b1 = (float)((double)bc[1] / a0);
    sc->b2 = (float)((double)bc[2] / a0);

    double cr = al, ci = be;   // c
    for (int i = 0; i < 3; ++i) { double nr = cr*cr - ci*ci, ni = 2.0*cr*ci; cr = nr; ci = ni; } // c^8
    double c8r = cr, c8i = ci;
    sc->c8 = make_float2((float)c8r, (float)c8i);
    for (int r = 0; r < 5; ++r) {
        sc->lvl[r] = make_float2((float)cr, (float)ci);
        double n = cr*cr + ci*ci;
        sc->ilvl[r] = make_float2((float)(cr / n), (float)(-ci / n));
        if (r == 0) sc->i8 = sc->ilvl[0];
        double nr = cr*cr - ci*ci, ni = 2.0*cr*ci; cr = nr; ci = ni;
    }
    // cr,ci = c^256
    sc->c256 = make_float2((float)cr, (float)ci);
    {
        double n = cr*cr + ci*ci;
        sc->ic256 = make_float2((float)(cr / n), (float)(-ci / n));
    }
    double c256r = cr, c256i = ci;
    for (int i = 0; i < 4; ++i) { double nr = cr*cr - ci*ci, ni = 2.0*cr*ci; cr = nr; ci = ni; } // c^4096
    sc->c4096r = cr; sc->c4096i = ci;
    // K0 = c^4096 * c^-8 = c^(8*511)
    {
        double n8 = c8r*c8r + c8i*c8i;
        double i8r = c8r / n8, i8i = -c8i / n8;
        sc->K0 = make_float2((float)(cr * i8r - ci * i8i), (float)(cr * i8i + ci * i8r));
    }
    for (int i = 0; i < 3; ++i) { double nr = cr*cr - ci*ci, ni = 2.0*cr*ci; cr = nr; ci = ni; } // c^32768
    sc->cBr = cr; sc->cBi = ci;
    (void)c256r; (void)c256i;
}

__device__ __forceinline__ float2 cmulf(float2 a, float2 b) {
    return make_float2(fmaf(a.x, b.x, -a.y * b.y), fmaf(a.x, b.y, a.y * b.x));
}

#define FIR8(f, va, vb, xm1, xm2, b0, b1, b2)                         \
    f[0] = fmaf(b1, xm1,  fmaf(b2, xm2,  b0 * va.x));                 \
    f[1] = fmaf(b1, va.x, fmaf(b2, xm1,  b0 * va.y));                 \
    f[2] = fmaf(b1, va.y, fmaf(b2, va.x, b0 * va.z));                 \
    f[3] = fmaf(b1, va.z, fmaf(b2, va.y, b0 * va.w));                 \
    f[4] = fmaf(b1, va.w, fmaf(b2, va.z, b0 * vb.x));                 \
    f[5] = fmaf(b1, vb.x, fmaf(b2, va.w, b0 * vb.y));                 \
    f[6] = fmaf(b1, vb.y, fmaf(b2, vb.x, b0 * vb.z));                 \
    f[7] = fmaf(b1, vb.z, fmaf(b2, vb.y, b0 * vb.w));

#define IIR8(y, f, na1, na2)                                          \
    y[0] = f[0];                                                      \
    y[1] = fmaf(na1, y[0], f[1]);                                     \
    y[2] = fmaf(na1, y[1], fmaf(na2, y[0], f[2]));                    \
    y[3] = fmaf(na1, y[2], fmaf(na2, y[1], f[3]));                    \
    y[4] = fmaf(na1, y[3], fmaf(na2, y[2], f[4]));                    \
    y[5] = fmaf(na1, y[4], fmaf(na2, y[3], f[5]));                    \
    y[6] = fmaf(na1, y[5], fmaf(na2, y[4], f[6]));                    \
    y[7] = fmaf(na1, y[6], fmaf(na2, y[5], f[7]));

__global__ __launch_bounds__(256, 4) void k_main(
    const float* __restrict__ x,
    const float* __restrict__ ac,
    const float* __restrict__ bc,
    const float* __restrict__ gainp,
    float* __restrict__ out)
{
    __shared__ SC sc;
    __shared__ float2  sWarpAgg[8];   // per-warp zero-IC u totals
    __shared__ float2  sEntry[8];     // corrected u entry per warp
    __shared__ double2 sE[8];         // zero-IC u state entering warp w

    int tid = threadIdx.x;
    int w = tid >> 5, lane = tid & 31;
    int bid = blockIdx.x;
    int row = bid >> 3, blkInRow = bid & 7;
    size_t base = (size_t)row * TT + (size_t)blkInRow * BLK;

    if (tid == 0) build_sc(ac, bc, &sc);
    __syncthreads();

    float na1 = sc.na1, na2 = sc.na2, b0 = sc.b0, b1 = sc.b1, b2 = sc.b2;
    float alpha = sc.alpha, beta = sc.beta, invbeta = sc.invbeta;
    float2 c256 = sc.c256;

    // Per-lane basis constants.
    float2 sd = sc.i8, su = make_float2(1.f, 0.f);
    if (lane & 1)  { sd = cmulf(sd, sc.ilvl[0]); su = cmulf(su, sc.lvl[0]); }
    if (lane & 2)  { sd = cmulf(sd, sc.ilvl[1]); su = cmulf(su, sc.lvl[1]); }
    if (lane & 4)  { sd = cmulf(sd, sc.ilvl[2]); su = cmulf(su, sc.lvl[2]); }
    if (lane & 8)  { sd = cmulf(sd, sc.ilvl[3]); su = cmulf(su, sc.lvl[3]); }
    if (lane & 16) { sd = cmulf(sd, sc.ilvl[4]); su = cmulf(su, sc.lvl[4]); }
    float2 sdA = cmulf(sd, sc.c8);   // c^(-8*lane) for phase A

    size_t wstart = base + (size_t)w * WSPAN;
    const float4* xv = reinterpret_cast<const float4*>(x + wstart);

    // Boundary x for this warp's span (global n<0 -> zeros).
    float bx1 = 0.f, bx2 = 0.f;
    if (blkInRow || w) { bx1 = x[wstart - 1]; bx2 = x[wstart - 2]; }

    // ---------------- Phase A: shuffle-free accumulate, one final reduce ----
    // U = sum_t K_t * sum_l c^(-8l) * b_{t,l},  K_t = c^(8*(511-32t)).
    {
        float pv_w = bx1, pv_z = bx2;
        float2 acc = make_float2(0.f, 0.f);
        float2 Kc = sc.K0;
        float2 ic256 = sc.ic256;
        float4 va = xv[2 * lane], vb = xv[2 * lane + 1];
#pragma unroll 4
        for (int t = 0; t < TILES; ++t) {
            float4 nva, nvb;
            if (t + 1 < TILES) {
                nva = xv[(t + 1) * 64 + 2 * lane];
                nvb = xv[(t + 1) * 64 + 2 * lane + 1];
            }
            float xm1 = __shfl_up_sync(0xffffffffu, vb.w, 1);
            float xm2 = __shfl_up_sync(0xffffffffu, vb.z, 1);
            if (lane == 0) { xm1 = pv_w; xm2 = pv_z; }

            float f[8], y[8];
            FIR8(f, va, vb, xm1, xm2, b0, b1, b2);
            IIR8(y, f, na1, na2);

            float2 u = make_float2(y[6], fmaf(alpha, y[6], -y[7]) * invbeta);
            float2 g = cmulf(u, Kc);        // uniform per-tile constant
            float2 h = cmulf(g, sdA);       // per-lane descale
            acc.x += h.x; acc.y += h.y;
            Kc = cmulf(Kc, ic256);

            pv_w = __shfl_sync(0xffffffffu, vb.w, 31);
            pv_z = __shfl_sync(0xffffffffu, vb.z, 31);
            va = nva; vb = nvb;
        }
        // single 5-round complex-sum reduce
#pragma unroll
        for (int s = 16; s > 0; s >>= 1) {
            acc.x += __shfl_down_sync(0xffffffffu, acc.x, s);
            acc.y += __shfl_down_sync(0xffffffffu, acc.y, s);
        }
        if (lane == 0) sWarpAgg[w] = acc;   // = warp zero-IC end state U (u-space)
    }
    __syncthreads();

    // ---------------- Thread 0: combine, publish, lookback, entries ----------------
    if (tid == 0) {
        double c4r = sc.c4096r, c4i = sc.c4096i;
        double cbr = sc.cBr, cbi = sc.cBi;
        double e1 = 0.0, e2 = 0.0;
#pragma unroll
        for (int ww = 0; ww < 8; ++ww) {
            sE[ww] = make_double2(e1, e2);
            float2 S = sWarpAgg[ww];
            double t1 = c4r * e1 - c4i * e2 + (double)S.x;
            double t2 = c4i * e1 + c4r * e2 + (double)S.y;
            e1 = t1; e2 = t2;
        }
        g_agg[bid] = make_float2((float)e1, (float)e2);
        __threadfence();

        double P1 = 0.0, P2 = 0.0;
        if (blkInRow == 0) {
            g_incl[bid] = make_float2((float)e1, (float)e2);
            __threadfence();
            *(volatile int*)&g_flag[bid] = 2;
        } else {
            *(volatile int*)&g_flag[bid] = 1;
            double M1 = 1.0, M2 = 0.0;
            int j = bid - 1;
            while (true) {
                int f;
                while ((f = *(volatile int*)&g_flag[j]) == 0) __nanosleep(32);
                __threadfence();
                volatile float* vp = (f == 2) ? (volatile float*)&g_incl[j]
                                              : (volatile float*)&g_agg[j];
                double Vx = (double)vp[0], Vy = (double)vp[1];
                P1 += M1 * Vx - M2 * Vy;
                P2 += M1 * Vy + M2 * Vx;
                if (f == 2) break;
                double m1 = M1 * cbr - M2 * cbi;
                M2 = M1 * cbi + M2 * cbr;
                M1 = m1;
                --j;
            }
            double i1 = cbr * P1 - cbi * P2 + e1;
            double i2 = cbi * P1 + cbr * P2 + e2;
            g_incl[bid] = make_float2((float)i1, (float)i2);
            __threadfence();
            *(volatile int*)&g_flag[bid] = 2;
        }
        // Per-warp corrected entries: entry_w = c^(4096*w) * P + E_w.
        double Q1 = P1, Q2 = P2;
#pragma unroll
        for (int ww = 0; ww < 8; ++ww) {
            double2 E = sE[ww];
            sEntry[ww] = make_float2((float)(Q1 + E.x), (float)(Q2 + E.y));
            double q1 = c4r * Q1 - c4i * Q2;
            Q2 = c4i * Q1 + c4r * Q2;
            Q1 = q1;
        }
    }
    __syncthreads();

    // ---------------- Phase C: corrected recompute + output ----------------
    {
        float gain = gainp[0];
        float2 C = sEntry[w];
        float4* ov = reinterpret_cast<float4*>(out + wstart);
        float pv_w = bx1, pv_z = bx2;
        float4 va = xv[2 * lane], vb = xv[2 * lane + 1];
#pragma unroll 4
        for (int t = 0; t < TILES; ++t) {
            float4 nva, nvb;
            if (t + 1 < TILES) {
                nva = xv[(t + 1) * 64 + 2 * lane];
                nvb = xv[(t + 1) * 64 + 2 * lane + 1];
            }
            float xm1 = __shfl_up_sync(0xffffffffu, vb.w, 1);
            float xm2 = __shfl_up_sync(0xffffffffu, vb.z, 1);
            if (lane == 0) { xm1 = pv_w; xm2 = pv_z; }

            float f[8], y[8];
            FIR8(f, va, vb, xm1, xm2, b0, b1, b2);
            IIR8(y, f, na1, na2);

            float2 u = make_float2(y[6], fmaf(alpha, y[6], -y[7]) * invbeta);
            float2 ww2 = cmulf(u, sd);
#pragma unroll
            for (int s = 1; s < 32; s <<= 1) {
                float px = __shfl_up_sync(0xffffffffu, ww2.x, s);
                float py = __shfl_up_sync(0xffffffffu, ww2.y, s);
                if (lane >= s) { ww2.x += px; ww2.y += py; }
            }
            float Sx = __shfl_sync(0xffffffffu, ww2.x, 31);
            float Sy = __shfl_sync(0xffffffffu, ww2.y, 31);
            float ex = __shfl_up_sync(0xffffffffu, ww2.x, 1);
            float ey = __shfl_up_sync(0xffffffffu, ww2.y, 1);
            if (lane == 0) { ex = 0.f; ey = 0.f; }

            float2 e = cmulf(make_float2(C.x + ex, C.y + ey), su);
            float yp1 = fmaf(alpha, e.x, -beta * e.y);
            float yp2 = e.x;

            float z0 = fmaf(na1, yp1, fmaf(na2, yp2, f[0]));
            float z1 = fmaf(na1, z0, fmaf(na2, yp1, f[1]));
            float z2 = fmaf(na1, z1, fmaf(na2, z0, f[2]));
            float z3 = fmaf(na1, z2, fmaf(na2, z1, f[3]));
            float z4 = fmaf(na1, z3, fmaf(na2, z2, f[4]));
            float z5 = fmaf(na1, z4, fmaf(na2, z3, f[5]));
            float z6 = fmaf(na1, z5, fmaf(na2, z4, f[6]));
            float z7 = fmaf(na1, z6, fmaf(na2, z5, f[7]));

            float4 oa, ob;
            oa.x = gain * fminf(1.f, fmaxf(-1.f, z0));
            oa.y = gain * fminf(1.f, fmaxf(-1.f, z1));
            oa.z = gain * fminf(1.f, fmaxf(-1.f, z2));
            oa.w = gain * fminf(1.f, fmaxf(-1.f, z3));
            ob.x = gain * fminf(1.f, fmaxf(-1.f, z4));
            ob.y = gain * fminf(1.f, fmaxf(-1.f, z5));
            ob.z = gain * fminf(1.f, fmaxf(-1.f, z6));
            ob.w = gain * fminf(1.f, fmaxf(-1.f, z7));
            __stcs(&ov[t * 64 + 2 * lane],     oa);
            __stcs(&ov[t * 64 + 2 * lane + 1], ob);

            C = cmulf(make_float2(C.x + Sx, C.y + Sy), c256);

            pv_w = __shfl_sync(0xffffffffu, vb.w, 31);
            pv_z = __shfl_sync(0xffffffffu, vb.z, 31);
            va = nva; vb = nvb;
        }
    }
}

extern "C" void kernel_launch(void* const* d_in, const int* in_sizes, int n_in,
                              void* d_out, int out_size)
{
    const float* x    = (const float*)d_in[0];
    const float* ac   = (const float*)d_in[1];
    const float* bc   = (const float*)d_in[2];
    const float* gain = (const float*)d_in[3];
    float* out = (float*)d_out;

    int* flagp;
    cudaGetSymbolAddress((void**)&flagp, g_flag);
    cudaMemsetAsync(flagp, 0, NBLK * sizeof(int));
    k_main<<<NBLK, 256>>>(x, ac, bc, gain, out);
}